// round 7
// baseline (speedup 1.0000x reference)
#include <cuda_runtime.h>
#include <cuda_bf16.h>
#include <cstdint>

// ============================================================================
// Split-bf16 (hi/lo) HMMA pipeline. Every GEMM is NT:
//   D[m][n] = sum_k A[m][k]*B[n][k],  D ~= AhBh + AhBl + AlBh  (fp32 accum)
// mma.sync.m16n8k16 bf16. CTA tile 128x128x64, 8 warps (2Mx4N),
// 3-stage cp.async pipeline (R4 skeleton), ldmatrix + double-buffered frags.
// ============================================================================

#define PADK 72                      // 64 data + 8 pad bf16 (144B rows)
#define TILE_ELT (128 * PADK)        // 9216 elements per operand tile
#define STG_ELT  (4 * TILE_ELT)      // Ah, Al, Bh, Bl
#define SMEM_REQ (3 * STG_ELT * 2)   // 221184 bytes

// ---- scratch (device globals) ----------------------------------------------
__device__ __align__(256) __nv_bfloat16 g_xT_hi[33554432],  g_xT_lo[33554432];
__device__ __align__(256) __nv_bfloat16 g_Wqkv_hi[50331648],g_Wqkv_lo[50331648];
__device__ __align__(256) __nv_bfloat16 g_Wq_hi[16777216],  g_Wq_lo[16777216];
__device__ __align__(256) __nv_bfloat16 g_Wk_hi[16777216],  g_Wk_lo[16777216];
__device__ __align__(256) __nv_bfloat16 g_Wv_hi[16777216],  g_Wv_lo[16777216];
__device__ __align__(256) __nv_bfloat16 g_Wout_hi[16777216],g_Wout_lo[16777216];
__device__ __align__(256) __nv_bfloat16 g_qkv_hi[100663296],g_qkv_lo[100663296];
__device__ __align__(256) __nv_bfloat16 g_q2_hi[33554432],  g_q2_lo[33554432];
__device__ __align__(256) __nv_bfloat16 g_k2_hi[33554432],  g_k2_lo[33554432];
__device__ __align__(256) __nv_bfloat16 g_v2T_hi[33554432], g_v2T_lo[33554432];
__device__ __align__(256) __nv_bfloat16 g_attn_hi[4194304], g_attn_lo[4194304];
__device__ __align__(256) __nv_bfloat16 g_outT_hi[33554432],g_outT_lo[33554432];
__device__ __align__(256) float g_dot[4194304];

// ---- helpers ----------------------------------------------------------------
__device__ __forceinline__ uint32_t smem_u32(const void* p) {
    uint32_t r;
    asm("{ .reg .u64 t; cvta.to.shared.u64 t, %1; cvt.u32.u64 %0, t; }" : "=r"(r) : "l"(p));
    return r;
}
__device__ __forceinline__ void cpasync16(uint32_t dst, const void* src) {
    asm volatile("cp.async.cg.shared.global [%0], [%1], 16;" :: "r"(dst), "l"(src));
}
__device__ __forceinline__ void ldmx4(uint32_t* r, uint32_t addr) {
    asm volatile("ldmatrix.sync.aligned.m8n8.x4.shared.b16 {%0,%1,%2,%3}, [%4];"
                 : "=r"(r[0]), "=r"(r[1]), "=r"(r[2]), "=r"(r[3]) : "r"(addr));
}
__device__ __forceinline__ void mma16816(float* c, const uint32_t* a, const uint32_t* b) {
    asm volatile(
        "mma.sync.aligned.m16n8k16.row.col.f32.bf16.bf16.f32 "
        "{%0,%1,%2,%3}, {%4,%5,%6,%7}, {%8,%9}, {%0,%1,%2,%3};"
        : "+f"(c[0]), "+f"(c[1]), "+f"(c[2]), "+f"(c[3])
        : "r"(a[0]), "r"(a[1]), "r"(a[2]), "r"(a[3]), "r"(b[0]), "r"(b[1]));
}
__device__ __forceinline__ void split2(float a, float b, uint32_t& hi, uint32_t& lo) {
    __nv_bfloat16 h0 = __float2bfloat16_rn(a), h1 = __float2bfloat16_rn(b);
    __nv_bfloat16 l0 = __float2bfloat16_rn(a - __bfloat162float(h0));
    __nv_bfloat16 l1 = __float2bfloat16_rn(b - __bfloat162float(h1));
    hi = (uint32_t)__bfloat16_as_ushort(h0) | ((uint32_t)__bfloat16_as_ushort(h1) << 16);
    lo = (uint32_t)__bfloat16_as_ushort(l0) | ((uint32_t)__bfloat16_as_ushort(l1) << 16);
}

// ---- GEMM -------------------------------------------------------------------
struct GemmP {
    int nk, ldA, ldB, zshift, zmask;
    int aZ1, aZ2, aConst;          // A row offset = aZ1*zh + aZ2*zl + aConst
    int bZ1, bZ2, bConst;
    long long cZ1, cZ2;            // C element offset
    int ldC, biasMode, outMode;    // bias: 0 none 1 perM 2 perN; out: 0 f32 1 split
    const float* bias;
    float* Cf;
    __nv_bfloat16* Chi; __nv_bfloat16* Clo;
    float alpha;
};

__global__ void __launch_bounds__(256, 1)
hmma_gemm(const __nv_bfloat16* __restrict__ Ahg, const __nv_bfloat16* __restrict__ Alg,
          const __nv_bfloat16* __restrict__ Bhg, const __nv_bfloat16* __restrict__ Blg,
          const GemmP p)
{
    extern __shared__ __align__(16) __nv_bfloat16 sm[];   // [3][4][128][PADK]
    const int tid = threadIdx.x, lane = tid & 31, wid = tid >> 5;
    const int wm = (wid & 1) * 64, wn = (wid >> 1) * 32;
    const int zh = blockIdx.z >> p.zshift, zl = blockIdx.z & p.zmask;
    const long long arow0 = (long long)p.aZ1 * zh + p.aZ2 * zl + p.aConst
                            + (long long)blockIdx.y * 128;
    const long long brow0 = (long long)p.bZ1 * zh + p.bZ2 * zl + p.bConst
                            + (long long)blockIdx.x * 128;
    const __nv_bfloat16* gAh = Ahg + arow0 * p.ldA;
    const __nv_bfloat16* gAl = Alg + arow0 * p.ldA;
    const __nv_bfloat16* gBh = Bhg + brow0 * p.ldB;
    const __nv_bfloat16* gBl = Blg + brow0 * p.ldB;
    const uint32_t smbase = smem_u32(sm);

    const int ldA = p.ldA, ldB = p.ldB, nk = p.nk;

    auto load_stage = [&](int st, int kb) {
        const uint32_t sb = smbase + (uint32_t)st * (STG_ELT * 2);
        const long long koff = (long long)kb * 64;
#pragma unroll
        for (int i = 0; i < 4; i++) {
            const int c = tid + i * 256;       // 0..1023
            const int row = c >> 3, ch = c & 7;
            const uint32_t doff = (uint32_t)(row * PADK + ch * 8) * 2;
            const long long ga = (long long)row * ldA + koff + ch * 8;
            const long long gb = (long long)row * ldB + koff + ch * 8;
            cpasync16(sb + 0 * (TILE_ELT * 2) + doff, gAh + ga);
            cpasync16(sb + 1 * (TILE_ELT * 2) + doff, gAl + ga);
            cpasync16(sb + 2 * (TILE_ELT * 2) + doff, gBh + gb);
            cpasync16(sb + 3 * (TILE_ELT * 2) + doff, gBl + gb);
        }
        asm volatile("cp.async.commit_group;" ::: "memory");
    };

    // prologue: 3 stages in flight (all stages have nk >= 3)
    load_stage(0, 0);
    load_stage(1, 1);
    load_stage(2, 2);

    float acc[4][4][4];
#pragma unroll
    for (int a = 0; a < 4; a++)
#pragma unroll
        for (int b = 0; b < 4; b++)
#pragma unroll
            for (int c = 0; c < 4; c++) acc[a][b][c] = 0.0f;

    // ldmatrix lane addressing
    const int lrow = lane & 15;            // row within 16-row group
    const int lcol = (lane >> 4) * 8;      // 0 or 8 (k-half)

    // double-buffered fragments
    uint32_t BhF[2][4][2], BlF[2][4][2];   // [buf][nt][b0/b1]
    uint32_t AhF[2][4],    AlF[2][4];      // [buf][a0..a3]

    for (int kb = 0; kb < nk; kb++) {
        asm volatile("cp.async.wait_group 2;" ::: "memory");
        __syncthreads();
        const int st = kb % 3;
        const uint32_t sAh = smbase + (uint32_t)st * (STG_ELT * 2);
        const uint32_t sAl = sAh + TILE_ELT * 2;
        const uint32_t sBh = sAl + TILE_ELT * 2;
        const uint32_t sBl = sBh + TILE_ELT * 2;

        // ---- prime fragments for k16=0 ----
        {
            const uint32_t kk = (uint32_t)lcol * 2;
#pragma unroll
            for (int pr = 0; pr < 2; pr++) {
                const uint32_t roff = (uint32_t)((wn + pr * 16 + lrow) * PADK) * 2 + kk;
                uint32_t r[4];
                ldmx4(r, sBh + roff);
                BhF[0][pr * 2 + 0][0] = r[0]; BhF[0][pr * 2 + 0][1] = r[2];
                BhF[0][pr * 2 + 1][0] = r[1]; BhF[0][pr * 2 + 1][1] = r[3];
                ldmx4(r, sBl + roff);
                BlF[0][pr * 2 + 0][0] = r[0]; BlF[0][pr * 2 + 0][1] = r[2];
                BlF[0][pr * 2 + 1][0] = r[1]; BlF[0][pr * 2 + 1][1] = r[3];
            }
            const uint32_t ra = (uint32_t)((wm + lrow) * PADK) * 2 + kk;
            ldmx4(&AhF[0][0], sAh + ra);
            ldmx4(&AlF[0][0], sAl + ra);
        }

#pragma unroll
        for (int k16 = 0; k16 < 4; k16++) {
            const int bcur = k16 & 1, bnxt = bcur ^ 1;
            // prefetch next k16's B fragments
            if (k16 < 3) {
                const uint32_t kk = (uint32_t)((k16 + 1) * 16 + lcol) * 2;
#pragma unroll
                for (int pr = 0; pr < 2; pr++) {
                    const uint32_t roff = (uint32_t)((wn + pr * 16 + lrow) * PADK) * 2 + kk;
                    uint32_t r[4];
                    ldmx4(r, sBh + roff);
                    BhF[bnxt][pr * 2 + 0][0] = r[0]; BhF[bnxt][pr * 2 + 0][1] = r[2];
                    BhF[bnxt][pr * 2 + 1][0] = r[1]; BhF[bnxt][pr * 2 + 1][1] = r[3];
                    ldmx4(r, sBl + roff);
                    BlF[bnxt][pr * 2 + 0][0] = r[0]; BlF[bnxt][pr * 2 + 0][1] = r[2];
                    BlF[bnxt][pr * 2 + 1][0] = r[1]; BlF[bnxt][pr * 2 + 1][1] = r[3];
                }
            }
#pragma unroll
            for (int mt = 0; mt < 4; mt++) {
                const int acur = mt & 1, anxt = acur ^ 1;
                // prefetch next A fragment (mt+1, or mt=0 of next k16)
                if (mt < 3) {
                    const uint32_t kk = (uint32_t)(k16 * 16 + lcol) * 2;
                    const uint32_t ra =
                        (uint32_t)((wm + (mt + 1) * 16 + lrow) * PADK) * 2 + kk;
                    ldmx4(&AhF[anxt][0], sAh + ra);
                    ldmx4(&AlF[anxt][0], sAl + ra);
                } else if (k16 < 3) {
                    const uint32_t kk = (uint32_t)((k16 + 1) * 16 + lcol) * 2;
                    const uint32_t ra = (uint32_t)((wm + lrow) * PADK) * 2 + kk;
                    ldmx4(&AhF[anxt][0], sAh + ra);
                    ldmx4(&AlF[anxt][0], sAl + ra);
                }
#pragma unroll
                for (int nt = 0; nt < 4; nt++) {
                    mma16816(acc[mt][nt], AhF[acur], BhF[bcur][nt]);
                    mma16816(acc[mt][nt], AhF[acur], BlF[bcur][nt]);
                    mma16816(acc[mt][nt], AlF[acur], BhF[bcur][nt]);
                }
            }
        }
        __syncthreads();
        if (kb + 3 < nk) load_stage(st, kb + 3);
    }

    // ---- epilogue ----
    const long long cbase = p.cZ1 * zh + p.cZ2 * zl;
    const int n0 = blockIdx.x * 128 + wn + (lane & 3) * 2;
    const int m0 = blockIdx.y * 128 + wm + (lane >> 2);
#pragma unroll
    for (int mt = 0; mt < 4; mt++) {
#pragma unroll
        for (int half = 0; half < 2; half++) {
            const int m = m0 + mt * 16 + half * 8;
            const float bm = (p.biasMode == 1) ? p.bias[m] : 0.0f;
            const long long rowoff = cbase + (long long)m * p.ldC;
#pragma unroll
            for (int nt = 0; nt < 4; nt++) {
                const int n = n0 + nt * 8;
                float v0 = acc[mt][nt][half * 2 + 0] * p.alpha + bm;
                float v1 = acc[mt][nt][half * 2 + 1] * p.alpha + bm;
                if (p.biasMode == 2) { v0 += p.bias[n]; v1 += p.bias[n + 1]; }
                if (p.outMode == 0) {
                    *(float2*)(p.Cf + rowoff + n) = make_float2(v0, v1);
                } else {
                    uint32_t h, l;
                    split2(v0, v1, h, l);
                    *(uint32_t*)(p.Chi + rowoff + n) = h;
                    *(uint32_t*)(p.Clo + rowoff + n) = l;
                }
            }
        }
    }
}

// ---- conversions -------------------------------------------------------------
__global__ void split_kernel(const float4* __restrict__ in, uint2* __restrict__ hi,
                             uint2* __restrict__ lo, int n4)
{
    int i = blockIdx.x * 256 + threadIdx.x;
    if (i >= n4) return;
    float4 v = in[i];
    uint32_t h0, l0, h1, l1;
    split2(v.x, v.y, h0, l0);
    split2(v.z, v.w, h1, l1);
    hi[i] = make_uint2(h0, h1);
    lo[i] = make_uint2(l0, l1);
}

// x[b][c][n] fp32 -> xT[b][n][c] split bf16 (4096x4096 per batch)
__global__ void transpose_split_kernel(const float* __restrict__ x,
                                       __nv_bfloat16* __restrict__ hi,
                                       __nv_bfloat16* __restrict__ lo)
{
    __shared__ float tile[32][33];
    const int b = blockIdx.z;
    const int c0 = blockIdx.y * 32, n0 = blockIdx.x * 32;
    const int tx = threadIdx.x, ty = threadIdx.y;
    const float* xb = x + (long long)b * 16777216;
#pragma unroll
    for (int i = 0; i < 4; i++)
        tile[ty + i * 8][tx] = xb[(long long)(c0 + ty + i * 8) * 4096 + n0 + tx];
    __syncthreads();
#pragma unroll
    for (int i = 0; i < 4; i++) {
        float v = tile[tx][ty + i * 8];
        __nv_bfloat16 h = __float2bfloat16_rn(v);
        __nv_bfloat16 l = __float2bfloat16_rn(v - __bfloat162float(h));
        long long o = (long long)b * 16777216 + (long long)(n0 + ty + i * 8) * 4096 + c0 + tx;
        hi[o] = h; lo[o] = l;
    }
}

// softmax over rows of 512, output split bf16
__global__ void softmax_split_kernel(const float* __restrict__ dot,
                                     __nv_bfloat16* __restrict__ hi,
                                     __nv_bfloat16* __restrict__ lo)
{
    const long long row = blockIdx.x;
    const float* p = dot + row * 512;
    __shared__ float red[256];
    const int t = threadIdx.x;
    float v0 = p[t], v1 = p[t + 256];
    red[t] = fmaxf(v0, v1); __syncthreads();
#pragma unroll
    for (int s = 128; s > 0; s >>= 1) {
        if (t < s) red[t] = fmaxf(red[t], red[t + s]);
        __syncthreads();
    }
    float mx = red[0]; __syncthreads();
    float e0 = expf(v0 - mx), e1 = expf(v1 - mx);
    red[t] = e0 + e1; __syncthreads();
#pragma unroll
    for (int s = 128; s > 0; s >>= 1) {
        if (t < s) red[t] += red[t + s];
        __syncthreads();
    }
    float inv = 1.0f / red[0];
    float a0 = e0 * inv, a1 = e1 * inv;
    __nv_bfloat16 h0 = __float2bfloat16_rn(a0);
    __nv_bfloat16 h1 = __float2bfloat16_rn(a1);
    hi[row * 512 + t]       = h0;
    hi[row * 512 + t + 256] = h1;
    lo[row * 512 + t]       = __float2bfloat16_rn(a0 - __bfloat162float(h0));
    lo[row * 512 + t + 256] = __float2bfloat16_rn(a1 - __bfloat162float(h1));
}

// ---- host --------------------------------------------------------------------
extern "C" void kernel_launch(void* const* d_in, const int* in_sizes, int n_in,
                              void* d_out, int out_size)
{
    const float* x    = (const float*)d_in[0];
    const float* Wqkv = (const float*)d_in[1];
    const float* bqkv = (const float*)d_in[2];
    const float* Wq   = (const float*)d_in[3];
    const float* bq   = (const float*)d_in[4];
    const float* Wk   = (const float*)d_in[5];
    const float* bk   = (const float*)d_in[6];
    const float* Wv   = (const float*)d_in[7];
    const float* bv   = (const float*)d_in[8];
    const float* Wout = (const float*)d_in[9];
    const float* bout = (const float*)d_in[10];
    float* y = (float*)d_out;

    __nv_bfloat16 *xT_h, *xT_l, *Wqkv_h, *Wqkv_l, *Wq_h, *Wq_l, *Wk_h, *Wk_l,
        *Wv_h, *Wv_l, *Wout_h, *Wout_l, *qkv_h, *qkv_l, *q2_h, *q2_l,
        *k2_h, *k2_l, *v2T_h, *v2T_l, *attn_h, *attn_l, *outT_h, *outT_l;
    float* dot;
    cudaGetSymbolAddress((void**)&xT_h,   g_xT_hi);   cudaGetSymbolAddress((void**)&xT_l,   g_xT_lo);
    cudaGetSymbolAddress((void**)&Wqkv_h, g_Wqkv_hi); cudaGetSymbolAddress((void**)&Wqkv_l, g_Wqkv_lo);
    cudaGetSymbolAddress((void**)&Wq_h,   g_Wq_hi);   cudaGetSymbolAddress((void**)&Wq_l,   g_Wq_lo);
    cudaGetSymbolAddress((void**)&Wk_h,   g_Wk_hi);   cudaGetSymbolAddress((void**)&Wk_l,   g_Wk_lo);
    cudaGetSymbolAddress((void**)&Wv_h,   g_Wv_hi);   cudaGetSymbolAddress((void**)&Wv_l,   g_Wv_lo);
    cudaGetSymbolAddress((void**)&Wout_h, g_Wout_hi); cudaGetSymbolAddress((void**)&Wout_l, g_Wout_lo);
    cudaGetSymbolAddress((void**)&qkv_h,  g_qkv_hi);  cudaGetSymbolAddress((void**)&qkv_l,  g_qkv_lo);
    cudaGetSymbolAddress((void**)&q2_h,   g_q2_hi);   cudaGetSymbolAddress((void**)&q2_l,   g_q2_lo);
    cudaGetSymbolAddress((void**)&k2_h,   g_k2_hi);   cudaGetSymbolAddress((void**)&k2_l,   g_k2_lo);
    cudaGetSymbolAddress((void**)&v2T_h,  g_v2T_hi);  cudaGetSymbolAddress((void**)&v2T_l,  g_v2T_lo);
    cudaGetSymbolAddress((void**)&attn_h, g_attn_hi); cudaGetSymbolAddress((void**)&attn_l, g_attn_lo);
    cudaGetSymbolAddress((void**)&outT_h, g_outT_hi); cudaGetSymbolAddress((void**)&outT_l, g_outT_lo);
    cudaGetSymbolAddress((void**)&dot,    g_dot);

    cudaFuncSetAttribute(hmma_gemm, cudaFuncAttributeMaxDynamicSharedMemorySize, SMEM_REQ);

    // conversions
    split_kernel<<<49152, 256>>>((const float4*)Wqkv, (uint2*)Wqkv_h, (uint2*)Wqkv_l, 12582912);
    split_kernel<<<16384, 256>>>((const float4*)Wq,   (uint2*)Wq_h,   (uint2*)Wq_l,   4194304);
    split_kernel<<<16384, 256>>>((const float4*)Wk,   (uint2*)Wk_h,   (uint2*)Wk_l,   4194304);
    split_kernel<<<16384, 256>>>((const float4*)Wv,   (uint2*)Wv_h,   (uint2*)Wv_l,   4194304);
    split_kernel<<<16384, 256>>>((const float4*)Wout, (uint2*)Wout_h, (uint2*)Wout_l, 4194304);
    transpose_split_kernel<<<dim3(128, 128, 2), dim3(32, 8)>>>(x, xT_h, xT_l);

    GemmP p;
    // Stage 1: qkv[b] = Wqkv @ xT[b]^T + bqkv -> split qkv [2][12288][4096]
    p = {64, 4096, 4096, 0, 0,  0, 0, 0,  4096, 0, 0,  50331648LL, 0,
         4096, 1, 1, bqkv, nullptr, qkv_h, qkv_l, 1.0f};
    hmma_gemm<<<dim3(32, 96, 2), 256, SMEM_REQ>>>(Wqkv_h, Wqkv_l, xT_h, xT_l, p);

    // Stage 2q: q2[z] = qkv_q[z] @ Wq^T + bq   (z = b*8+h)
    p = {64, 4096, 4096, 3, 7,  12288, 512, 0,  0, 0, 0,  16777216LL, 2097152LL,
         4096, 2, 1, bq, nullptr, q2_h, q2_l, 1.0f};
    hmma_gemm<<<dim3(32, 4, 16), 256, SMEM_REQ>>>(qkv_h, qkv_l, Wq_h, Wq_l, p);
    // Stage 2k
    p = {64, 4096, 4096, 3, 7,  12288, 512, 4096,  0, 0, 0,  16777216LL, 2097152LL,
         4096, 2, 1, bk, nullptr, k2_h, k2_l, 1.0f};
    hmma_gemm<<<dim3(32, 4, 16), 256, SMEM_REQ>>>(qkv_h, qkv_l, Wk_h, Wk_l, p);
    // Stage 2v (transposed): v2T[b][h][m][d] = Wv[m] . v[z][d] + bv[m]
    p = {64, 4096, 4096, 3, 7,  0, 0, 0,  12288, 512, 8192,  16777216LL, 2097152LL,
         512, 1, 1, bv, nullptr, v2T_h, v2T_l, 1.0f};
    hmma_gemm<<<dim3(4, 32, 16), 256, SMEM_REQ>>>(Wv_h, Wv_l, qkv_h, qkv_l, p);

    // Stage 3: dot[z] = q2[z] @ k2[z]^T * 0.125 -> fp32
    p = {64, 4096, 4096, 3, 7,  4096, 512, 0,  4096, 512, 0,  2097152LL, 262144LL,
         512, 0, 0, nullptr, dot, nullptr, nullptr, 0.125f};
    hmma_gemm<<<dim3(4, 4, 16), 256, SMEM_REQ>>>(q2_h, q2_l, k2_h, k2_l, p);

    // Stage 4: softmax + split
    softmax_split_kernel<<<8192, 256>>>(dot, attn_h, attn_l);

    // Stage 5 (transposed): outT[b][m][h*512+c] = v2T[z][m] . attn[z][c]
    p = {8, 512, 512, 3, 7,  32768, 4096, 0,  4096, 512, 0,  16777216LL, 512LL,
         4096, 0, 1, nullptr, nullptr, outT_h, outT_l, 1.0f};
    hmma_gemm<<<dim3(4, 32, 16), 256, SMEM_REQ>>>(v2T_h, v2T_l, attn_h, attn_l, p);

    // Stage 6: y[b] = Wout @ outT[b]^T + bout -> fp32 d_out
    p = {64, 4096, 4096, 0, 0,  0, 0, 0,  4096, 0, 0,  16777216LL, 0,
         4096, 1, 0, bout, y, nullptr, nullptr, 1.0f};
    hmma_gemm<<<dim3(32, 32, 2), 256, SMEM_REQ>>>(Wout_h, Wout_l, outT_h, outT_l, p);

    (void)in_sizes; (void)n_in; (void)out_size;
}

// round 8
// speedup vs baseline: 1.2500x; 1.2500x over previous
#include <cuda_runtime.h>
#include <cuda_bf16.h>
#include <cstdint>

// ============================================================================
// Split-bf16 (hi/lo) HMMA pipeline. Every GEMM is NT:
//   D[m][n] = sum_k A[m][k]*B[n][k],  D ~= AhBh + AhBl + AlBh  (fp32 accum)
// mma.sync.m16n8k16 bf16. CTA tile 256x128x64, 8 warps (4Mx2N, 64x64 each),
// 2-stage cp.async pipeline, plain LDS fragment loads (R4-style).
// ============================================================================

#define PADK 72                          // 64 data + 8 pad bf16 (144B rows)
#define A_TILE_ELT (256 * PADK)          // 18432
#define B_TILE_ELT (128 * PADK)          // 9216
#define STG_ELT (2 * A_TILE_ELT + 2 * B_TILE_ELT)   // 55296 elements
#define STG_BYTES (STG_ELT * 2)          // 110592
#define SMEM_REQ (2 * STG_BYTES)         // 221184
#define OFF_AL (A_TILE_ELT * 2)
#define OFF_BH (2 * A_TILE_ELT * 2)
#define OFF_BL (2 * A_TILE_ELT * 2 + B_TILE_ELT * 2)

// ---- scratch (device globals) ----------------------------------------------
__device__ __align__(256) __nv_bfloat16 g_xT_hi[33554432],  g_xT_lo[33554432];
__device__ __align__(256) __nv_bfloat16 g_Wqkv_hi[50331648],g_Wqkv_lo[50331648];
__device__ __align__(256) __nv_bfloat16 g_Wq_hi[16777216],  g_Wq_lo[16777216];
__device__ __align__(256) __nv_bfloat16 g_Wk_hi[16777216],  g_Wk_lo[16777216];
__device__ __align__(256) __nv_bfloat16 g_Wv_hi[16777216],  g_Wv_lo[16777216];
__device__ __align__(256) __nv_bfloat16 g_Wout_hi[16777216],g_Wout_lo[16777216];
__device__ __align__(256) __nv_bfloat16 g_qkv_hi[100663296],g_qkv_lo[100663296];
__device__ __align__(256) __nv_bfloat16 g_q2_hi[33554432],  g_q2_lo[33554432];
__device__ __align__(256) __nv_bfloat16 g_k2_hi[33554432],  g_k2_lo[33554432];
__device__ __align__(256) __nv_bfloat16 g_v2T_hi[33554432], g_v2T_lo[33554432];
__device__ __align__(256) __nv_bfloat16 g_attn_hi[4194304], g_attn_lo[4194304];
__device__ __align__(256) __nv_bfloat16 g_outT_hi[33554432],g_outT_lo[33554432];
__device__ __align__(256) float g_dot[4194304];

// ---- helpers ----------------------------------------------------------------
__device__ __forceinline__ uint32_t smem_u32(const void* p) {
    uint32_t r;
    asm("{ .reg .u64 t; cvta.to.shared.u64 t, %1; cvt.u32.u64 %0, t; }" : "=r"(r) : "l"(p));
    return r;
}
__device__ __forceinline__ void cpasync16(uint32_t dst, const void* src) {
    asm volatile("cp.async.cg.shared.global [%0], [%1], 16;" :: "r"(dst), "l"(src));
}
__device__ __forceinline__ void mma16816(float* c, const uint32_t* a, const uint32_t* b) {
    asm volatile(
        "mma.sync.aligned.m16n8k16.row.col.f32.bf16.bf16.f32 "
        "{%0,%1,%2,%3}, {%4,%5,%6,%7}, {%8,%9}, {%0,%1,%2,%3};"
        : "+f"(c[0]), "+f"(c[1]), "+f"(c[2]), "+f"(c[3])
        : "r"(a[0]), "r"(a[1]), "r"(a[2]), "r"(a[3]), "r"(b[0]), "r"(b[1]));
}
__device__ __forceinline__ void split2(float a, float b, uint32_t& hi, uint32_t& lo) {
    __nv_bfloat16 h0 = __float2bfloat16_rn(a), h1 = __float2bfloat16_rn(b);
    __nv_bfloat16 l0 = __float2bfloat16_rn(a - __bfloat162float(h0));
    __nv_bfloat16 l1 = __float2bfloat16_rn(b - __bfloat162float(h1));
    hi = (uint32_t)__bfloat16_as_ushort(h0) | ((uint32_t)__bfloat16_as_ushort(h1) << 16);
    lo = (uint32_t)__bfloat16_as_ushort(l0) | ((uint32_t)__bfloat16_as_ushort(l1) << 16);
}

// ---- GEMM -------------------------------------------------------------------
struct GemmP {
    int nk, ldA, ldB, zshift, zmask;
    int aZ1, aZ2, aConst;          // A row offset = aZ1*zh + aZ2*zl + aConst
    int bZ1, bZ2, bConst;
    long long cZ1, cZ2;            // C element offset
    int ldC, biasMode, outMode;    // bias: 0 none 1 perM 2 perN; out: 0 f32 1 split
    const float* bias;
    float* Cf;
    __nv_bfloat16* Chi; __nv_bfloat16* Clo;
    float alpha;
};

__global__ void __launch_bounds__(256, 1)
hmma_gemm(const __nv_bfloat16* __restrict__ Ahg, const __nv_bfloat16* __restrict__ Alg,
          const __nv_bfloat16* __restrict__ Bhg, const __nv_bfloat16* __restrict__ Blg,
          const GemmP p)
{
    extern __shared__ __align__(16) __nv_bfloat16 sm[];   // [2 stages]
    const int tid = threadIdx.x, lane = tid & 31, wid = tid >> 5;
    const int wm = (wid >> 1) * 64, wn = (wid & 1) * 64;
    const int zh = blockIdx.z >> p.zshift, zl = blockIdx.z & p.zmask;
    const long long arow0 = (long long)p.aZ1 * zh + p.aZ2 * zl + p.aConst
                            + (long long)blockIdx.y * 256;
    const long long brow0 = (long long)p.bZ1 * zh + p.bZ2 * zl + p.bConst
                            + (long long)blockIdx.x * 128;
    const __nv_bfloat16* gAh = Ahg + arow0 * p.ldA;
    const __nv_bfloat16* gAl = Alg + arow0 * p.ldA;
    const __nv_bfloat16* gBh = Bhg + brow0 * p.ldB;
    const __nv_bfloat16* gBl = Blg + brow0 * p.ldB;
    const uint32_t smbase = smem_u32(sm);

    const int ldA = p.ldA, ldB = p.ldB, nk = p.nk;

    auto load_stage = [&](int st, int kb) {
        const uint32_t sb = smbase + (uint32_t)st * STG_BYTES;
        const long long koff = (long long)kb * 64;
        // A tiles: 256 rows x 8 chunks = 2048 chunks per type
#pragma unroll
        for (int i = 0; i < 8; i++) {
            const int c = tid + i * 256;
            const int row = c >> 3, ch = c & 7;
            const uint32_t doff = (uint32_t)(row * PADK + ch * 8) * 2;
            const long long ga = (long long)row * ldA + koff + ch * 8;
            cpasync16(sb + doff, gAh + ga);
            cpasync16(sb + OFF_AL + doff, gAl + ga);
        }
        // B tiles: 128 rows x 8 chunks = 1024 chunks per type
#pragma unroll
        for (int i = 0; i < 4; i++) {
            const int c = tid + i * 256;
            const int row = c >> 3, ch = c & 7;
            const uint32_t doff = (uint32_t)(row * PADK + ch * 8) * 2;
            const long long gb = (long long)row * ldB + koff + ch * 8;
            cpasync16(sb + OFF_BH + doff, gBh + gb);
            cpasync16(sb + OFF_BL + doff, gBl + gb);
        }
        asm volatile("cp.async.commit_group;" ::: "memory");
    };

    // prologue: 2 stages in flight (all stages have nk >= 2)
    load_stage(0, 0);
    load_stage(1, 1);

    float acc[4][8][4];
#pragma unroll
    for (int a = 0; a < 4; a++)
#pragma unroll
        for (int b = 0; b < 8; b++)
#pragma unroll
            for (int c = 0; c < 4; c++) acc[a][b][c] = 0.0f;

    const int krow = (lane & 3) * 2;     // k within 16
    const int grow = lane >> 2;          // row within 8

    for (int kb = 0; kb < nk; kb++) {
        asm volatile("cp.async.wait_group 1;" ::: "memory");
        __syncthreads();
        const int st = kb & 1;
        const __nv_bfloat16* sAh = sm + (size_t)st * STG_ELT;
        const __nv_bfloat16* sAl = sAh + A_TILE_ELT;
        const __nv_bfloat16* sBh = sAl + A_TILE_ELT;
        const __nv_bfloat16* sBl = sBh + B_TILE_ELT;

#pragma unroll
        for (int k16 = 0; k16 < 4; k16++) {
            const int kk = k16 * 16 + krow;
            // ---- A fragments for all 4 mt (hi & lo) ----
            uint32_t ah[4][4], al[4][4];
#pragma unroll
            for (int mt = 0; mt < 4; mt++) {
                const int r0 = (wm + mt * 16 + grow) * PADK;
                const int r1 = r0 + 8 * PADK;
                ah[mt][0] = *(const uint32_t*)(sAh + r0 + kk);
                ah[mt][1] = *(const uint32_t*)(sAh + r1 + kk);
                ah[mt][2] = *(const uint32_t*)(sAh + r0 + kk + 8);
                ah[mt][3] = *(const uint32_t*)(sAh + r1 + kk + 8);
                al[mt][0] = *(const uint32_t*)(sAl + r0 + kk);
                al[mt][1] = *(const uint32_t*)(sAl + r1 + kk);
                al[mt][2] = *(const uint32_t*)(sAl + r0 + kk + 8);
                al[mt][3] = *(const uint32_t*)(sAl + r1 + kk + 8);
            }
            // ---- per nt: load B frag, 12 MMAs reusing it across mt ----
#pragma unroll
            for (int nt = 0; nt < 8; nt++) {
                const int r = (wn + nt * 8 + grow) * PADK;
                uint32_t bh[2], bl[2];
                bh[0] = *(const uint32_t*)(sBh + r + kk);
                bh[1] = *(const uint32_t*)(sBh + r + kk + 8);
                bl[0] = *(const uint32_t*)(sBl + r + kk);
                bl[1] = *(const uint32_t*)(sBl + r + kk + 8);
#pragma unroll
                for (int mt = 0; mt < 4; mt++) {
                    mma16816(acc[mt][nt], ah[mt], bh);
                    mma16816(acc[mt][nt], ah[mt], bl);
                    mma16816(acc[mt][nt], al[mt], bh);
                }
            }
        }
        __syncthreads();
        if (kb + 2 < nk) load_stage(st, kb + 2);
    }

    // ---- epilogue ----
    const long long cbase = p.cZ1 * zh + p.cZ2 * zl;
    const int n0 = blockIdx.x * 128 + wn + (lane & 3) * 2;
    const int m0 = blockIdx.y * 256 + wm + (lane >> 2);
#pragma unroll
    for (int mt = 0; mt < 4; mt++) {
#pragma unroll
        for (int half = 0; half < 2; half++) {
            const int m = m0 + mt * 16 + half * 8;
            const float bm = (p.biasMode == 1) ? p.bias[m] : 0.0f;
            const long long rowoff = cbase + (long long)m * p.ldC;
#pragma unroll
            for (int nt = 0; nt < 8; nt++) {
                const int n = n0 + nt * 8;
                float v0 = acc[mt][nt][half * 2 + 0] * p.alpha + bm;
                float v1 = acc[mt][nt][half * 2 + 1] * p.alpha + bm;
                if (p.biasMode == 2) { v0 += p.bias[n]; v1 += p.bias[n + 1]; }
                if (p.outMode == 0) {
                    *(float2*)(p.Cf + rowoff + n) = make_float2(v0, v1);
                } else {
                    uint32_t h, l;
                    split2(v0, v1, h, l);
                    *(uint32_t*)(p.Chi + rowoff + n) = h;
                    *(uint32_t*)(p.Clo + rowoff + n) = l;
                }
            }
        }
    }
}

// ---- conversions -------------------------------------------------------------
__global__ void split_kernel(const float4* __restrict__ in, uint2* __restrict__ hi,
                             uint2* __restrict__ lo, int n4)
{
    int i = blockIdx.x * 256 + threadIdx.x;
    if (i >= n4) return;
    float4 v = in[i];
    uint32_t h0, l0, h1, l1;
    split2(v.x, v.y, h0, l0);
    split2(v.z, v.w, h1, l1);
    hi[i] = make_uint2(h0, h1);
    lo[i] = make_uint2(l0, l1);
}

// x[b][c][n] fp32 -> xT[b][n][c] split bf16 (4096x4096 per batch)
__global__ void transpose_split_kernel(const float* __restrict__ x,
                                       __nv_bfloat16* __restrict__ hi,
                                       __nv_bfloat16* __restrict__ lo)
{
    __shared__ float tile[32][33];
    const int b = blockIdx.z;
    const int c0 = blockIdx.y * 32, n0 = blockIdx.x * 32;
    const int tx = threadIdx.x, ty = threadIdx.y;
    const float* xb = x + (long long)b * 16777216;
#pragma unroll
    for (int i = 0; i < 4; i++)
        tile[ty + i * 8][tx] = xb[(long long)(c0 + ty + i * 8) * 4096 + n0 + tx];
    __syncthreads();
#pragma unroll
    for (int i = 0; i < 4; i++) {
        float v = tile[tx][ty + i * 8];
        __nv_bfloat16 h = __float2bfloat16_rn(v);
        __nv_bfloat16 l = __float2bfloat16_rn(v - __bfloat162float(h));
        long long o = (long long)b * 16777216 + (long long)(n0 + ty + i * 8) * 4096 + c0 + tx;
        hi[o] = h; lo[o] = l;
    }
}

// softmax over rows of 512, output split bf16
__global__ void softmax_split_kernel(const float* __restrict__ dot,
                                     __nv_bfloat16* __restrict__ hi,
                                     __nv_bfloat16* __restrict__ lo)
{
    const long long row = blockIdx.x;
    const float* p = dot + row * 512;
    __shared__ float red[256];
    const int t = threadIdx.x;
    float v0 = p[t], v1 = p[t + 256];
    red[t] = fmaxf(v0, v1); __syncthreads();
#pragma unroll
    for (int s = 128; s > 0; s >>= 1) {
        if (t < s) red[t] = fmaxf(red[t], red[t + s]);
        __syncthreads();
    }
    float mx = red[0]; __syncthreads();
    float e0 = expf(v0 - mx), e1 = expf(v1 - mx);
    red[t] = e0 + e1; __syncthreads();
#pragma unroll
    for (int s = 128; s > 0; s >>= 1) {
        if (t < s) red[t] += red[t + s];
        __syncthreads();
    }
    float inv = 1.0f / red[0];
    float a0 = e0 * inv, a1 = e1 * inv;
    __nv_bfloat16 h0 = __float2bfloat16_rn(a0);
    __nv_bfloat16 h1 = __float2bfloat16_rn(a1);
    hi[row * 512 + t]       = h0;
    hi[row * 512 + t + 256] = h1;
    lo[row * 512 + t]       = __float2bfloat16_rn(a0 - __bfloat162float(h0));
    lo[row * 512 + t + 256] = __float2bfloat16_rn(a1 - __bfloat162float(h1));
}

// ---- host --------------------------------------------------------------------
extern "C" void kernel_launch(void* const* d_in, const int* in_sizes, int n_in,
                              void* d_out, int out_size)
{
    const float* x    = (const float*)d_in[0];
    const float* Wqkv = (const float*)d_in[1];
    const float* bqkv = (const float*)d_in[2];
    const float* Wq   = (const float*)d_in[3];
    const float* bq   = (const float*)d_in[4];
    const float* Wk   = (const float*)d_in[5];
    const float* bk   = (const float*)d_in[6];
    const float* Wv   = (const float*)d_in[7];
    const float* bv   = (const float*)d_in[8];
    const float* Wout = (const float*)d_in[9];
    const float* bout = (const float*)d_in[10];
    float* y = (float*)d_out;

    __nv_bfloat16 *xT_h, *xT_l, *Wqkv_h, *Wqkv_l, *Wq_h, *Wq_l, *Wk_h, *Wk_l,
        *Wv_h, *Wv_l, *Wout_h, *Wout_l, *qkv_h, *qkv_l, *q2_h, *q2_l,
        *k2_h, *k2_l, *v2T_h, *v2T_l, *attn_h, *attn_l, *outT_h, *outT_l;
    float* dot;
    cudaGetSymbolAddress((void**)&xT_h,   g_xT_hi);   cudaGetSymbolAddress((void**)&xT_l,   g_xT_lo);
    cudaGetSymbolAddress((void**)&Wqkv_h, g_Wqkv_hi); cudaGetSymbolAddress((void**)&Wqkv_l, g_Wqkv_lo);
    cudaGetSymbolAddress((void**)&Wq_h,   g_Wq_hi);   cudaGetSymbolAddress((void**)&Wq_l,   g_Wq_lo);
    cudaGetSymbolAddress((void**)&Wk_h,   g_Wk_hi);   cudaGetSymbolAddress((void**)&Wk_l,   g_Wk_lo);
    cudaGetSymbolAddress((void**)&Wv_h,   g_Wv_hi);   cudaGetSymbolAddress((void**)&Wv_l,   g_Wv_lo);
    cudaGetSymbolAddress((void**)&Wout_h, g_Wout_hi); cudaGetSymbolAddress((void**)&Wout_l, g_Wout_lo);
    cudaGetSymbolAddress((void**)&qkv_h,  g_qkv_hi);  cudaGetSymbolAddress((void**)&qkv_l,  g_qkv_lo);
    cudaGetSymbolAddress((void**)&q2_h,   g_q2_hi);   cudaGetSymbolAddress((void**)&q2_l,   g_q2_lo);
    cudaGetSymbolAddress((void**)&k2_h,   g_k2_hi);   cudaGetSymbolAddress((void**)&k2_l,   g_k2_lo);
    cudaGetSymbolAddress((void**)&v2T_h,  g_v2T_hi);  cudaGetSymbolAddress((void**)&v2T_l,  g_v2T_lo);
    cudaGetSymbolAddress((void**)&attn_h, g_attn_hi); cudaGetSymbolAddress((void**)&attn_l, g_attn_lo);
    cudaGetSymbolAddress((void**)&outT_h, g_outT_hi); cudaGetSymbolAddress((void**)&outT_l, g_outT_lo);
    cudaGetSymbolAddress((void**)&dot,    g_dot);

    cudaFuncSetAttribute(hmma_gemm, cudaFuncAttributeMaxDynamicSharedMemorySize, SMEM_REQ);

    // conversions
    split_kernel<<<49152, 256>>>((const float4*)Wqkv, (uint2*)Wqkv_h, (uint2*)Wqkv_l, 12582912);
    split_kernel<<<16384, 256>>>((const float4*)Wq,   (uint2*)Wq_h,   (uint2*)Wq_l,   4194304);
    split_kernel<<<16384, 256>>>((const float4*)Wk,   (uint2*)Wk_h,   (uint2*)Wk_l,   4194304);
    split_kernel<<<16384, 256>>>((const float4*)Wv,   (uint2*)Wv_h,   (uint2*)Wv_l,   4194304);
    split_kernel<<<16384, 256>>>((const float4*)Wout, (uint2*)Wout_h, (uint2*)Wout_l, 4194304);
    transpose_split_kernel<<<dim3(128, 128, 2), dim3(32, 8)>>>(x, xT_h, xT_l);

    GemmP p;
    // Stage 1: qkv[b] = Wqkv @ xT[b]^T + bqkv -> split qkv [2][12288][4096]
    p = {64, 4096, 4096, 0, 0,  0, 0, 0,  4096, 0, 0,  50331648LL, 0,
         4096, 1, 1, bqkv, nullptr, qkv_h, qkv_l, 1.0f};
    hmma_gemm<<<dim3(32, 48, 2), 256, SMEM_REQ>>>(Wqkv_h, Wqkv_l, xT_h, xT_l, p);

    // Stage 2q: q2[z] = qkv_q[z] @ Wq^T + bq   (z = b*8+h)
    p = {64, 4096, 4096, 3, 7,  12288, 512, 0,  0, 0, 0,  16777216LL, 2097152LL,
         4096, 2, 1, bq, nullptr, q2_h, q2_l, 1.0f};
    hmma_gemm<<<dim3(32, 2, 16), 256, SMEM_REQ>>>(qkv_h, qkv_l, Wq_h, Wq_l, p);
    // Stage 2k
    p = {64, 4096, 4096, 3, 7,  12288, 512, 4096,  0, 0, 0,  16777216LL, 2097152LL,
         4096, 2, 1, bk, nullptr, k2_h, k2_l, 1.0f};
    hmma_gemm<<<dim3(32, 2, 16), 256, SMEM_REQ>>>(qkv_h, qkv_l, Wk_h, Wk_l, p);
    // Stage 2v (transposed): v2T[b][h][m][d] = Wv[m] . v[z][d] + bv[m]
    p = {64, 4096, 4096, 3, 7,  0, 0, 0,  12288, 512, 8192,  16777216LL, 2097152LL,
         512, 1, 1, bv, nullptr, v2T_h, v2T_l, 1.0f};
    hmma_gemm<<<dim3(4, 16, 16), 256, SMEM_REQ>>>(Wv_h, Wv_l, qkv_h, qkv_l, p);

    // Stage 3: dot[z] = q2[z] @ k2[z]^T * 0.125 -> fp32
    p = {64, 4096, 4096, 3, 7,  4096, 512, 0,  4096, 512, 0,  2097152LL, 262144LL,
         512, 0, 0, nullptr, dot, nullptr, nullptr, 0.125f};
    hmma_gemm<<<dim3(4, 2, 16), 256, SMEM_REQ>>>(q2_h, q2_l, k2_h, k2_l, p);

    // Stage 4: softmax + split
    softmax_split_kernel<<<8192, 256>>>(dot, attn_h, attn_l);

    // Stage 5 (transposed): outT[b][m][h*512+c] = v2T[z][m] . attn[z][c]
    p = {8, 512, 512, 3, 7,  32768, 4096, 0,  4096, 512, 0,  16777216LL, 512LL,
         4096, 0, 1, nullptr, nullptr, outT_h, outT_l, 1.0f};
    hmma_gemm<<<dim3(4, 16, 16), 256, SMEM_REQ>>>(v2T_h, v2T_l, attn_h, attn_l, p);

    // Stage 6: y[b] = Wout @ outT[b]^T + bout -> fp32 d_out
    p = {64, 4096, 4096, 0, 0,  0, 0, 0,  4096, 0, 0,  16777216LL, 0,
         4096, 1, 0, bout, y, nullptr, nullptr, 1.0f};
    hmma_gemm<<<dim3(32, 16, 2), 256, SMEM_REQ>>>(Wout_h, Wout_l, outT_h, outT_l, p);

    (void)in_sizes; (void)n_in; (void)out_size;
}